// round 10
// baseline (speedup 1.0000x reference)
#include <cuda_runtime.h>
#include <math.h>
#include <stdint.h>

#define AA 3072          // A = BS * IA
#define DD 2048          // D = BS * (IA-1)
#define NB 1024          // BS
#define NBLK 296         // persistent grid: 2 CTAs/SM * 148 SMs
#define NWARP (NBLK * 8) // 2368 global warps

__device__ float g_buf0[AA];
__device__ float g_buf1[AA];
__device__ unsigned g_bar;    // zero-init; reset at end of every run
__device__ unsigned g_exit;

__device__ __forceinline__ uint64_t mk_evict_last_policy() {
    uint64_t pol;
    asm("createpolicy.fractional.L2::evict_last.b64 %0, 1.0;" : "=l"(pol));
    return pol;
}

// bulk prefetch into L2 with evict_last policy (fire & forget, TMA path)
__device__ __forceinline__ void l2_pf(const void* p, uint32_t bytes, uint64_t pol) {
    asm volatile("cp.async.bulk.prefetch.L2.global.L2::cache_hint [%0], %1, %2;"
                 :: "l"(p), "r"(bytes), "l"(pol) : "memory");
}

// ---------------------------------------------------------------------------
// grid-wide barrier (all NBLK blocks resident -> spin is safe)
// ---------------------------------------------------------------------------
__device__ __forceinline__ void grid_bar(int tid, unsigned target) {
    __threadfence();
    __syncthreads();
    if (tid == 0) {
        atomicAdd(&g_bar, 1u);
        while (*(volatile unsigned*)&g_bar < target) { }
        __threadfence();
    }
    __syncthreads();
}

// ---------------------------------------------------------------------------
// one row dot-product: deep double-buffered LDG.128 pipeline (8 in flight)
// ACT: 0 none, 1 tanh, 2 tanhshrink
// ---------------------------------------------------------------------------
template<int ACT, int COLS>
__device__ __forceinline__ void dot_row(const float* __restrict__ W,
                                        const float* __restrict__ sx,
                                        const float* __restrict__ b,
                                        float* __restrict__ y,
                                        int row, int lane)
{
    constexpr int NBATCH = COLS / 4 / 32 / 8;   // 3 (COLS=3072) or 2 (2048)
    const float4* __restrict__ W4 =
        reinterpret_cast<const float4*>(W + (size_t)row * COLS);
    const float4* __restrict__ sx4 = reinterpret_cast<const float4*>(sx);

    float4 buf[2][8];
    #pragma unroll
    for (int t = 0; t < 8; ++t)
        buf[0][t] = __ldcs(&W4[lane + 32 * t]);

    float a0 = 0.f, a1 = 0.f, a2 = 0.f, a3 = 0.f;
    #pragma unroll
    for (int bt = 0; bt < NBATCH; ++bt) {
        const int cur = bt & 1;
        if (bt + 1 < NBATCH) {
            #pragma unroll
            for (int t = 0; t < 8; ++t)
                buf[cur ^ 1][t] = __ldcs(&W4[lane + 32 * (8 * (bt + 1) + t)]);
        }
        #pragma unroll
        for (int t = 0; t < 8; ++t) {
            float4 v = sx4[lane + 32 * (8 * bt + t)];
            a0 = fmaf(buf[cur][t].x, v.x, a0);
            a1 = fmaf(buf[cur][t].y, v.y, a1);
            a2 = fmaf(buf[cur][t].z, v.z, a2);
            a3 = fmaf(buf[cur][t].w, v.w, a3);
        }
    }
    float acc = (a0 + a1) + (a2 + a3);
    #pragma unroll
    for (int off = 16; off; off >>= 1)
        acc += __shfl_xor_sync(0xFFFFFFFFu, acc, off);

    if (lane == 0) {
        float h = acc + b[row];
        if (ACT == 1)      h = tanhf(h);
        else if (ACT == 2) h = h - tanhf(h);
        y[row] = h;
    }
}

// ---------------------------------------------------------------------------
// layer: stage x to smem, then alternate { compute row of W ; bulk-prefetch
// row of nextW } so the prefetch stream runs concurrently with demand and
// is paced across the whole layer.
// ---------------------------------------------------------------------------
template<int ACT, int COLS, int ROWS>
__device__ __forceinline__ void layer(const float* __restrict__ W,
                                      const float* __restrict__ xg,
                                      const float* __restrict__ b,
                                      float* __restrict__ y,
                                      float* sx, int tid, int gw, int lane,
                                      const float* __restrict__ nextW,
                                      int prows, int pcols, uint64_t pol)
{
    const float4* __restrict__ xg4 = reinterpret_cast<const float4*>(xg);
    float4* sx4 = reinterpret_cast<float4*>(sx);
    for (int k = tid; k < COLS / 4; k += 256) sx4[k] = __ldg(&xg4[k]);
    __syncthreads();

    int r = gw, p = gw;
    while (r < ROWS || p < prows) {
        if (r < ROWS) {
            dot_row<ACT, COLS>(W, sx, b, y, r, lane);
            r += NWARP;
        }
        if (lane == 0 && p < prows)
            l2_pf(nextW + (size_t)p * pcols, (uint32_t)(pcols * 4), pol);
        p += NWARP;
    }
}

// pdist chunk: out[i*1024+j] = ||a[i]-a[j]||
template<int DIMS>
__device__ __forceinline__ void pdist_fused(const float* __restrict__ a,
                                            float* __restrict__ outp,
                                            float* s, int tid, int bid)
{
    __syncthreads();
    for (int t = tid; t < NB * DIMS; t += 256) s[t] = a[t];
    __syncthreads();
    for (int idx = bid * 256 + tid; idx < NB * NB; idx += NBLK * 256) {
        const int i = idx >> 10;
        const int j = idx & (NB - 1);
        float d2 = 0.f;
        #pragma unroll
        for (int k = 0; k < DIMS; ++k) {
            float d = s[i * DIMS + k] - s[j * DIMS + k];
            d2 = fmaf(d, d, d2);
        }
        outp[idx] = sqrtf(d2);
    }
}

// ---------------------------------------------------------------------------
// the whole network in one persistent kernel, software-pipelined weight
// prefetch (layer i compute || layer i+1 DRAM stream)
// ---------------------------------------------------------------------------
__global__ void __launch_bounds__(256, 2)
fused_net(const float* __restrict__ x,
          const float* __restrict__ ew1, const float* __restrict__ eb1,
          const float* __restrict__ ew2, const float* __restrict__ eb2,
          const float* __restrict__ ew3, const float* __restrict__ eb3,
          const float* __restrict__ ew4, const float* __restrict__ eb4,
          const float* __restrict__ dw1, const float* __restrict__ db1,
          const float* __restrict__ dw2, const float* __restrict__ db2,
          const float* __restrict__ dw3, const float* __restrict__ db3,
          const float* __restrict__ dw4, const float* __restrict__ db4,
          float* __restrict__ out)
{
    __shared__ float sx[AA];    // 12 KB: layer input / pdist points

    const int tid  = threadIdx.x;
    const int bid  = blockIdx.x;
    const int lane = tid & 31;
    const int gw   = bid * 8 + (tid >> 5);
    const uint64_t pol = mk_evict_last_policy();

    float* out_main = out;                      // 3072
    float* out_ind  = out + AA;                 // 1024*1024
    float* out_lat  = out + AA + NB * NB;       // 1024*1024
    float* y        = out + AA + 2 * NB * NB;   // 2048 (lat_repr)

    // L1: x -> buf0 (tanh) || prefetch ew2
    layer<1, AA, AA>(ew1, x, eb1, g_buf0, sx, tid, gw, lane, ew2, AA, AA, pol);
    grid_bar(tid, NBLK * 1);

    // L2: buf0 -> buf1 (tanh) || prefetch ew3
    layer<1, AA, AA>(ew2, g_buf0, eb2, g_buf1, sx, tid, gw, lane, ew3, AA, AA, pol);
    grid_bar(tid, NBLK * 2);

    // L3: buf1 -> buf0 (none) || prefetch ew4
    layer<0, AA, AA>(ew3, g_buf1, eb3, g_buf0, sx, tid, gw, lane, ew4, DD, AA, pol);
    grid_bar(tid, NBLK * 3);

    // L4: buf0 -> y (tanhshrink, 2048 rows) || prefetch dw1
    layer<2, AA, DD>(ew4, g_buf0, eb4, y, sx, tid, gw, lane, dw1, AA, DD, pol);
    grid_bar(tid, NBLK * 4);

    // L5: y -> buf0 (tanh, COLS=2048) || prefetch dw2
    layer<1, DD, AA>(dw1, y, db1, g_buf0, sx, tid, gw, lane, dw2, AA, AA, pol);
    grid_bar(tid, NBLK * 5);

    // L6: buf0 -> buf1 (tanh) || prefetch dw3
    layer<1, AA, AA>(dw2, g_buf0, db2, g_buf1, sx, tid, gw, lane, dw3, AA, AA, pol);
    grid_bar(tid, NBLK * 6);

    // L7: buf1 -> buf0 (none) || prefetch dw4
    layer<0, AA, AA>(dw3, g_buf1, db3, g_buf0, sx, tid, gw, lane, dw4, AA, AA, pol);
    grid_bar(tid, NBLK * 7);

    // L8: buf0 -> out_main (tanh) || prefetch ew1 for the NEXT graph replay
    layer<1, AA, AA>(dw4, g_buf0, db4, out_main, sx, tid, gw, lane, ew1, AA, AA, pol);

    // pdists (x stable; y stable & visible via barriers 5..7)
    pdist_fused<3>(x, out_ind, sx, tid, bid);
    pdist_fused<2>(y, out_lat, sx, tid, bid);

    // exit: last block resets barrier counters for the next replay
    __syncthreads();
    if (tid == 0) {
        unsigned done = atomicAdd(&g_exit, 1u);
        if (done == NBLK - 1) {
            g_bar  = 0;
            g_exit = 0;
            __threadfence();
        }
    }
}

// ---------------------------------------------------------------------------
extern "C" void kernel_launch(void* const* d_in, const int* in_sizes, int n_in,
                              void* d_out, int out_size)
{
    (void)in_sizes; (void)n_in; (void)out_size;

    fused_net<<<NBLK, 256>>>(
        (const float*)d_in[0],
        (const float*)d_in[1],  (const float*)d_in[2],
        (const float*)d_in[3],  (const float*)d_in[4],
        (const float*)d_in[5],  (const float*)d_in[6],
        (const float*)d_in[7],  (const float*)d_in[8],
        (const float*)d_in[9],  (const float*)d_in[10],
        (const float*)d_in[11], (const float*)d_in[12],
        (const float*)d_in[13], (const float*)d_in[14],
        (const float*)d_in[15], (const float*)d_in[16],
        (float*)d_out);
}

// round 13
// speedup vs baseline: 1.0506x; 1.0506x over previous
#include <cuda_runtime.h>
#include <math.h>
#include <stdint.h>

#define AA 3072          // A = BS * IA
#define DD 2048          // D = BS * (IA-1)
#define NB 1024          // BS
#define NBLK 296         // persistent grid: 2 CTAs/SM * 148 SMs
#define NWARP (NBLK * 8) // 2368 global warps

__device__ float g_buf0[AA];
__device__ float g_buf1[AA];
__device__ unsigned g_bar;    // zero-init; reset at end of every run
__device__ unsigned g_exit;

// fire-and-forget bulk prefetch into L2 (TMA engine path, no SMEM, no wait)
__device__ __forceinline__ void l2_pf(const void* p, uint32_t bytes) {
    asm volatile("cp.async.bulk.prefetch.L2.global [%0], %1;"
                 :: "l"(p), "r"(bytes) : "memory");
}

// ---------------------------------------------------------------------------
// grid-wide barrier (all NBLK blocks resident -> spin is safe)
// ---------------------------------------------------------------------------
__device__ __forceinline__ void grid_bar(int tid, unsigned target) {
    __threadfence();
    __syncthreads();
    if (tid == 0) {
        atomicAdd(&g_bar, 1u);
        while (*(volatile unsigned*)&g_bar < target) { }
        __threadfence();
    }
    __syncthreads();
}

// ---------------------------------------------------------------------------
// one row dot-product: deep double-buffered LDG.128 pipeline (8 in flight)
// ACT: 0 none, 1 tanh, 2 tanhshrink
// ---------------------------------------------------------------------------
template<int ACT, int COLS>
__device__ __forceinline__ void dot_row(const float* __restrict__ W,
                                        const float* __restrict__ sx,
                                        const float* __restrict__ b,
                                        float* __restrict__ y,
                                        int row, int lane)
{
    constexpr int NBATCH = COLS / 4 / 32 / 8;   // 3 (COLS=3072) or 2 (2048)
    const float4* __restrict__ W4 =
        reinterpret_cast<const float4*>(W + (size_t)row * COLS);
    const float4* __restrict__ sx4 = reinterpret_cast<const float4*>(sx);

    float4 buf[2][8];
    #pragma unroll
    for (int t = 0; t < 8; ++t)
        buf[0][t] = __ldcs(&W4[lane + 32 * t]);

    float a0 = 0.f, a1 = 0.f, a2 = 0.f, a3 = 0.f;
    #pragma unroll
    for (int bt = 0; bt < NBATCH; ++bt) {
        const int cur = bt & 1;
        if (bt + 1 < NBATCH) {
            #pragma unroll
            for (int t = 0; t < 8; ++t)
                buf[cur ^ 1][t] = __ldcs(&W4[lane + 32 * (8 * (bt + 1) + t)]);
        }
        #pragma unroll
        for (int t = 0; t < 8; ++t) {
            float4 v = sx4[lane + 32 * (8 * bt + t)];
            a0 = fmaf(buf[cur][t].x, v.x, a0);
            a1 = fmaf(buf[cur][t].y, v.y, a1);
            a2 = fmaf(buf[cur][t].z, v.z, a2);
            a3 = fmaf(buf[cur][t].w, v.w, a3);
        }
    }
    float acc = (a0 + a1) + (a2 + a3);
    #pragma unroll
    for (int off = 16; off; off >>= 1)
        acc += __shfl_xor_sync(0xFFFFFFFFu, acc, off);

    if (lane == 0) {
        float h = acc + b[row];
        if (ACT == 1)      h = tanhf(h);
        else if (ACT == 2) h = h - tanhf(h);
        y[row] = h;
    }
}

// ---------------------------------------------------------------------------
// layer: stage x into smem; per warp, SELF-prefetch this layer's row r+2*NWARP
// via the bulk path while demand-computing row r. Demand LDGs then hit L2
// (shorter latency -> ~2x effective demand BW for the same MSHR budget),
// while DRAM is fed by the independent TMA-engine prefetch stream.
// ---------------------------------------------------------------------------
template<int ACT, int COLS, int ROWS>
__device__ __forceinline__ void layer(const float* __restrict__ W,
                                      const float* __restrict__ xg,
                                      const float* __restrict__ b,
                                      float* __restrict__ y,
                                      float* sx, int tid, int gw, int lane)
{
    const float4* __restrict__ xg4 = reinterpret_cast<const float4*>(xg);
    float4* sx4 = reinterpret_cast<float4*>(sx);
    for (int k = tid; k < COLS / 4; k += 256) sx4[k] = __ldg(&xg4[k]);
    __syncthreads();

    // prologue: prime the pipe one row ahead
    if (lane == 0 && gw + NWARP < ROWS)
        l2_pf(W + (size_t)(gw + NWARP) * COLS, (uint32_t)(COLS * 4));

    for (int row = gw; row < ROWS; row += NWARP) {
        if (lane == 0 && row + 2 * NWARP < ROWS)
            l2_pf(W + (size_t)(row + 2 * NWARP) * COLS, (uint32_t)(COLS * 4));
        dot_row<ACT, COLS>(W, sx, b, y, row, lane);
    }
}

// fire-and-forget prefetch of a whole matrix's rows owned by this warp
__device__ __forceinline__ void prefetch_rows(const float* W, int rows, int cols,
                                              int gw, int lane)
{
    if (lane == 0)
        for (int r = gw; r < rows; r += NWARP)
            l2_pf(W + (size_t)r * cols, (uint32_t)(cols * 4));
}

// pdist chunk: out[i*1024+j] = ||a[i]-a[j]||
template<int DIMS>
__device__ __forceinline__ void pdist_fused(const float* __restrict__ a,
                                            float* __restrict__ outp,
                                            float* s, int tid, int bid)
{
    __syncthreads();
    for (int t = tid; t < NB * DIMS; t += 256) s[t] = a[t];
    __syncthreads();
    for (int idx = bid * 256 + tid; idx < NB * NB; idx += NBLK * 256) {
        const int i = idx >> 10;
        const int j = idx & (NB - 1);
        float d2 = 0.f;
        #pragma unroll
        for (int k = 0; k < DIMS; ++k) {
            float d = s[i * DIMS + k] - s[j * DIMS + k];
            d2 = fmaf(d, d, d2);
        }
        outp[idx] = sqrtf(d2);
    }
}

// ---------------------------------------------------------------------------
// the whole network in one persistent kernel (R9 base + intra-layer
// self-prefetch)
// ---------------------------------------------------------------------------
__global__ void __launch_bounds__(256, 2)
fused_net(const float* __restrict__ x,
          const float* __restrict__ ew1, const float* __restrict__ eb1,
          const float* __restrict__ ew2, const float* __restrict__ eb2,
          const float* __restrict__ ew3, const float* __restrict__ eb3,
          const float* __restrict__ ew4, const float* __restrict__ eb4,
          const float* __restrict__ dw1, const float* __restrict__ db1,
          const float* __restrict__ dw2, const float* __restrict__ db2,
          const float* __restrict__ dw3, const float* __restrict__ db3,
          const float* __restrict__ dw4, const float* __restrict__ db4,
          float* __restrict__ out)
{
    __shared__ float sx[AA];    // 12 KB: layer input / pdist points

    const int tid  = threadIdx.x;
    const int bid  = blockIdx.x;
    const int lane = tid & 31;
    const int gw   = bid * 8 + (tid >> 5);

    float* out_main = out;                      // 3072
    float* out_ind  = out + AA;                 // 1024*1024
    float* out_lat  = out + AA + NB * NB;       // 1024*1024
    float* y        = out + AA + 2 * NB * NB;   // 2048 (lat_repr)

    layer<1, AA, AA>(ew1, x,      eb1, g_buf0,   sx, tid, gw, lane);
    grid_bar(tid, NBLK * 1);
    layer<1, AA, AA>(ew2, g_buf0, eb2, g_buf1,   sx, tid, gw, lane);
    grid_bar(tid, NBLK * 2);
    layer<0, AA, AA>(ew3, g_buf1, eb3, g_buf0,   sx, tid, gw, lane);
    grid_bar(tid, NBLK * 3);
    layer<2, AA, DD>(ew4, g_buf0, eb4, y,        sx, tid, gw, lane);
    grid_bar(tid, NBLK * 4);
    layer<1, DD, AA>(dw1, y,      db1, g_buf0,   sx, tid, gw, lane);
    grid_bar(tid, NBLK * 5);
    layer<1, AA, AA>(dw2, g_buf0, db2, g_buf1,   sx, tid, gw, lane);
    grid_bar(tid, NBLK * 6);
    layer<0, AA, AA>(dw3, g_buf1, db3, g_buf0,   sx, tid, gw, lane);
    grid_bar(tid, NBLK * 7);
    layer<1, AA, AA>(dw4, g_buf0, db4, out_main, sx, tid, gw, lane);

    // warm ew1 in L2 for the NEXT graph replay (fires during pdist work)
    prefetch_rows(ew1, AA, AA, gw, lane);

    // pdists (x const input; y written at L4, published by bars 5..7)
    pdist_fused<3>(x, out_ind, sx, tid, bid);
    pdist_fused<2>(y, out_lat, sx, tid, bid);

    // exit: last block resets barrier counters for next replay
    __syncthreads();
    if (tid == 0) {
        unsigned done = atomicAdd(&g_exit, 1u);
        if (done == NBLK - 1) {
            g_bar  = 0;
            g_exit = 0;
            __threadfence();
        }
    }
}

// ---------------------------------------------------------------------------
extern "C" void kernel_launch(void* const* d_in, const int* in_sizes, int n_in,
                              void* d_out, int out_size)
{
    (void)in_sizes; (void)n_in; (void)out_size;

    fused_net<<<NBLK, 256>>>(
        (const float*)d_in[0],
        (const float*)d_in[1],  (const float*)d_in[2],
        (const float*)d_in[3],  (const float*)d_in[4],
        (const float*)d_in[5],  (const float*)d_in[6],
        (const float*)d_in[7],  (const float*)d_in[8],
        (const float*)d_in[9],  (const float*)d_in[10],
        (const float*)d_in[11], (const float*)d_in[12],
        (const float*)d_in[13], (const float*)d_in[14],
        (const float*)d_in[15], (const float*)d_in[16],
        (float*)d_out);
}

// round 14
// speedup vs baseline: 1.1091x; 1.0557x over previous
#include <cuda_runtime.h>
#include <math.h>
#include <stdint.h>

#define AA 3072          // A = BS * IA
#define DD 2048          // D = BS * (IA-1)
#define NB 1024          // BS
#define NBLK 296         // persistent grid: 2 CTAs/SM * 148 SMs
#define NWARP (NBLK * 8) // 2368 global warps

__device__ float g_buf0[AA];
__device__ float g_buf1[AA];
__device__ unsigned g_bar;    // zero-init; reset at end of every run
__device__ unsigned g_exit;

// ---------------------------------------------------------------------------
// grid-wide barrier (all NBLK blocks resident -> spin is safe)
// ---------------------------------------------------------------------------
__device__ __forceinline__ void grid_bar(int tid, unsigned target) {
    __threadfence();
    __syncthreads();
    if (tid == 0) {
        atomicAdd(&g_bar, 1u);
        while (*(volatile unsigned*)&g_bar < target) { }
        __threadfence();
    }
    __syncthreads();
}

// ---------------------------------------------------------------------------
// one row dot-product: deep double-buffered LDG.128 pipeline (8 in flight)
// ACT: 0 none, 1 tanh, 2 tanhshrink
// ---------------------------------------------------------------------------
template<int ACT, int COLS>
__device__ __forceinline__ void dot_row(const float* __restrict__ W,
                                        const float* __restrict__ sx,
                                        const float* __restrict__ b,
                                        float* __restrict__ y,
                                        int row, int lane)
{
    constexpr int NBATCH = COLS / 4 / 32 / 8;   // 3 (COLS=3072) or 2 (2048)
    const float4* __restrict__ W4 =
        reinterpret_cast<const float4*>(W + (size_t)row * COLS);
    const float4* __restrict__ sx4 = reinterpret_cast<const float4*>(sx);

    float4 buf[2][8];
    #pragma unroll
    for (int t = 0; t < 8; ++t)
        buf[0][t] = __ldcs(&W4[lane + 32 * t]);

    float a0 = 0.f, a1 = 0.f, a2 = 0.f, a3 = 0.f;
    #pragma unroll
    for (int bt = 0; bt < NBATCH; ++bt) {
        const int cur = bt & 1;
        if (bt + 1 < NBATCH) {
            #pragma unroll
            for (int t = 0; t < 8; ++t)
                buf[cur ^ 1][t] = __ldcs(&W4[lane + 32 * (8 * (bt + 1) + t)]);
        }
        #pragma unroll
        for (int t = 0; t < 8; ++t) {
            float4 v = sx4[lane + 32 * (8 * bt + t)];
            a0 = fmaf(buf[cur][t].x, v.x, a0);
            a1 = fmaf(buf[cur][t].y, v.y, a1);
            a2 = fmaf(buf[cur][t].z, v.z, a2);
            a3 = fmaf(buf[cur][t].w, v.w, a3);
        }
    }
    float acc = (a0 + a1) + (a2 + a3);
    #pragma unroll
    for (int off = 16; off; off >>= 1)
        acc += __shfl_xor_sync(0xFFFFFFFFu, acc, off);

    if (lane == 0) {
        float h = acc + b[row];
        if (ACT == 1)      h = tanhf(h);
        else if (ACT == 2) h = h - tanhf(h);
        y[row] = h;
    }
}

// ---------------------------------------------------------------------------
// layer: stage x into smem, compute this warp's rows
// ---------------------------------------------------------------------------
template<int ACT, int COLS, int ROWS>
__device__ __forceinline__ void layer(const float* __restrict__ W,
                                      const float* __restrict__ xg,
                                      const float* __restrict__ b,
                                      float* __restrict__ y,
                                      float* sx, int tid, int gw, int lane)
{
    const float4* __restrict__ xg4 = reinterpret_cast<const float4*>(xg);
    float4* sx4 = reinterpret_cast<float4*>(sx);
    for (int k = tid; k < COLS / 4; k += 256) sx4[k] = __ldg(&xg4[k]);
    __syncthreads();
    for (int row = gw; row < ROWS; row += NWARP)
        dot_row<ACT, COLS>(W, sx, b, y, row, lane);
}

// ---------------------------------------------------------------------------
// warp-local pdist slice (NO barriers): runs in the tail bubble of a layer,
// reading the point set straight from the already-staged sx.
// out[i*1024+j] = || p[i] - p[j] ||_2
// ---------------------------------------------------------------------------
template<int DIMS>
__device__ __forceinline__ void pdist_warp(const float* __restrict__ s,
                                           float* __restrict__ outp,
                                           int gw, int lane)
{
    for (int idx = gw * 32 + lane; idx < NB * NB; idx += NWARP * 32) {
        const int i = idx >> 10;
        const int j = idx & (NB - 1);
        float d2 = 0.f;
        #pragma unroll
        for (int k = 0; k < DIMS; ++k) {
            float d = s[i * DIMS + k] - s[j * DIMS + k];
            d2 = fmaf(d, d, d2);
        }
        outp[idx] = sqrtf(d2);
    }
}

// ---------------------------------------------------------------------------
// the whole network in one persistent kernel; pdists folded into the
// load-imbalance bubbles of L1 (x resident in sx) and L5 (y resident in sx)
// ---------------------------------------------------------------------------
__global__ void __launch_bounds__(256, 2)
fused_net(const float* __restrict__ x,
          const float* __restrict__ ew1, const float* __restrict__ eb1,
          const float* __restrict__ ew2, const float* __restrict__ eb2,
          const float* __restrict__ ew3, const float* __restrict__ eb3,
          const float* __restrict__ ew4, const float* __restrict__ eb4,
          const float* __restrict__ dw1, const float* __restrict__ db1,
          const float* __restrict__ dw2, const float* __restrict__ db2,
          const float* __restrict__ dw3, const float* __restrict__ db3,
          const float* __restrict__ dw4, const float* __restrict__ db4,
          float* __restrict__ out)
{
    __shared__ float sx[AA];    // 12 KB: layer input (x in L1, y in L5)

    const int tid  = threadIdx.x;
    const int bid  = blockIdx.x;
    const int lane = tid & 31;
    const int gw   = bid * 8 + (tid >> 5);

    float* out_main = out;                      // 3072
    float* out_ind  = out + AA;                 // 1024*1024
    float* out_lat  = out + AA + NB * NB;       // 1024*1024
    float* y        = out + AA + 2 * NB * NB;   // 2048 (lat_repr)

    // L1: x -> buf0 (tanh); bubble: pdist on in_data (sx == x)
    layer<1, AA, AA>(ew1, x, eb1, g_buf0, sx, tid, gw, lane);
    pdist_warp<3>(sx, out_ind, gw, lane);
    grid_bar(tid, NBLK * 1);

    // L2: buf0 -> buf1 (tanh)
    layer<1, AA, AA>(ew2, g_buf0, eb2, g_buf1, sx, tid, gw, lane);
    grid_bar(tid, NBLK * 2);

    // L3: buf1 -> buf0 (none)
    layer<0, AA, AA>(ew3, g_buf1, eb3, g_buf0, sx, tid, gw, lane);
    grid_bar(tid, NBLK * 3);

    // L4: buf0 -> y (tanhshrink, 2048 rows)
    layer<2, AA, DD>(ew4, g_buf0, eb4, y, sx, tid, gw, lane);
    grid_bar(tid, NBLK * 4);

    // L5: y -> buf0 (tanh, COLS=2048); bubble: pdist on lat_repr (sx == y)
    layer<1, DD, AA>(dw1, y, db1, g_buf0, sx, tid, gw, lane);
    pdist_warp<2>(sx, out_lat, gw, lane);
    grid_bar(tid, NBLK * 5);

    // L6: buf0 -> buf1 (tanh)
    layer<1, AA, AA>(dw2, g_buf0, db2, g_buf1, sx, tid, gw, lane);
    grid_bar(tid, NBLK * 6);

    // L7: buf1 -> buf0 (none)
    layer<0, AA, AA>(dw3, g_buf1, db3, g_buf0, sx, tid, gw, lane);
    grid_bar(tid, NBLK * 7);

    // L8: buf0 -> out_main (tanh)
    layer<1, AA, AA>(dw4, g_buf0, db4, out_main, sx, tid, gw, lane);

    // exit: last block resets barrier counters for next replay
    __syncthreads();
    if (tid == 0) {
        unsigned done = atomicAdd(&g_exit, 1u);
        if (done == NBLK - 1) {
            g_bar  = 0;
            g_exit = 0;
            __threadfence();
        }
    }
}

// ---------------------------------------------------------------------------
extern "C" void kernel_launch(void* const* d_in, const int* in_sizes, int n_in,
                              void* d_out, int out_size)
{
    (void)in_sizes; (void)n_in; (void)out_size;

    fused_net<<<NBLK, 256>>>(
        (const float*)d_in[0],
        (const float*)d_in[1],  (const float*)d_in[2],
        (const float*)d_in[3],  (const float*)d_in[4],
        (const float*)d_in[5],  (const float*)d_in[6],
        (const float*)d_in[7],  (const float*)d_in[8],
        (const float*)d_in[9],  (const float*)d_in[10],
        (const float*)d_in[11], (const float*)d_in[12],
        (const float*)d_in[13], (const float*)d_in[14],
        (const float*)d_in[15], (const float*)d_in[16],
        (float*)d_out);
}

// round 15
// speedup vs baseline: 1.1577x; 1.0438x over previous
#include <cuda_runtime.h>
#include <math.h>
#include <stdint.h>

#define AA 3072          // A = BS * IA
#define DD 2048          // D = BS * (IA-1)
#define NB 1024          // BS
#define NBLK 296         // persistent grid: 2 CTAs/SM * 148 SMs
#define NWARP (NBLK * 8) // 2368 global warps

__device__ float g_buf0[AA];
__device__ float g_buf1[AA];
__device__ unsigned g_bar;    // zero-init; reset at end of every run
__device__ unsigned g_exit;

// ---------------------------------------------------------------------------
// grid-wide barrier (all NBLK blocks resident): release/acquire, no membar
// ---------------------------------------------------------------------------
__device__ __forceinline__ void grid_bar(int tid, unsigned target) {
    __syncthreads();                      // block's work complete
    if (tid == 0) {
        asm volatile("red.release.gpu.global.add.u32 [%0], 1;"
                     :: "l"(&g_bar) : "memory");
        unsigned v;
        do {
            asm volatile("ld.acquire.gpu.global.u32 %0, [%1];"
                         : "=r"(v) : "l"(&g_bar));
        } while (v < target);
    }
    __syncthreads();                      // broadcast release to whole block
}

// ---------------------------------------------------------------------------
// single-row dot: deep double-buffered LDG.128 pipeline (8 in flight)
// ACT: 0 none, 1 tanh, 2 tanhshrink
// ---------------------------------------------------------------------------
template<int ACT>
__device__ __forceinline__ float act_apply(float h) {
    if (ACT == 1)      return tanhf(h);
    if (ACT == 2)      return h - tanhf(h);
    return h;
}

template<int ACT, int COLS>
__device__ __forceinline__ void dot_row(const float* __restrict__ W,
                                        const float* __restrict__ sx,
                                        const float* __restrict__ b,
                                        float* __restrict__ y,
                                        int row, int lane)
{
    constexpr int NBATCH = COLS / 4 / 32 / 8;   // 3 (3072) or 2 (2048)
    const float4* __restrict__ W4 =
        reinterpret_cast<const float4*>(W + (size_t)row * COLS);
    const float4* __restrict__ sx4 = reinterpret_cast<const float4*>(sx);

    float4 buf[2][8];
    #pragma unroll
    for (int t = 0; t < 8; ++t)
        buf[0][t] = __ldcs(&W4[lane + 32 * t]);

    float a0 = 0.f, a1 = 0.f, a2 = 0.f, a3 = 0.f;
    #pragma unroll
    for (int bt = 0; bt < NBATCH; ++bt) {
        const int cur = bt & 1;
        if (bt + 1 < NBATCH) {
            #pragma unroll
            for (int t = 0; t < 8; ++t)
                buf[cur ^ 1][t] = __ldcs(&W4[lane + 32 * (8 * (bt + 1) + t)]);
        }
        #pragma unroll
        for (int t = 0; t < 8; ++t) {
            float4 v = sx4[lane + 32 * (8 * bt + t)];
            a0 = fmaf(buf[cur][t].x, v.x, a0);
            a1 = fmaf(buf[cur][t].y, v.y, a1);
            a2 = fmaf(buf[cur][t].z, v.z, a2);
            a3 = fmaf(buf[cur][t].w, v.w, a3);
        }
    }
    float acc = (a0 + a1) + (a2 + a3);
    #pragma unroll
    for (int off = 16; off; off >>= 1)
        acc += __shfl_xor_sync(0xFFFFFFFFu, acc, off);

    if (lane == 0)
        y[row] = act_apply<ACT>(acc + b[row]);
}

// ---------------------------------------------------------------------------
// two-row interleaved dot: both rows stream concurrently (4-deep per row,
// 8 loads in flight total) -> no serial second-row tail; sx read shared.
// ---------------------------------------------------------------------------
template<int ACT, int COLS>
__device__ __forceinline__ void dot_row2(const float* __restrict__ W,
                                         const float* __restrict__ sx,
                                         const float* __restrict__ b,
                                         float* __restrict__ y,
                                         int row0, int row1, int lane)
{
    constexpr int NB2 = COLS / 4 / 32 / 4;   // 6 (3072) or 4 (2048)
    const float4* __restrict__ A4 =
        reinterpret_cast<const float4*>(W + (size_t)row0 * COLS);
    const float4* __restrict__ B4 =
        reinterpret_cast<const float4*>(W + (size_t)row1 * COLS);
    const float4* __restrict__ sx4 = reinterpret_cast<const float4*>(sx);

    float4 ba[2][4], bb[2][4];
    #pragma unroll
    for (int t = 0; t < 4; ++t) {
        ba[0][t] = __ldcs(&A4[lane + 32 * t]);
        bb[0][t] = __ldcs(&B4[lane + 32 * t]);
    }

    float a0 = 0.f, a1 = 0.f, a2 = 0.f, a3 = 0.f;
    float c0 = 0.f, c1 = 0.f, c2 = 0.f, c3 = 0.f;
    #pragma unroll
    for (int bt = 0; bt < NB2; ++bt) {
        const int cur = bt & 1;
        if (bt + 1 < NB2) {
            #pragma unroll
            for (int t = 0; t < 4; ++t) {
                ba[cur ^ 1][t] = __ldcs(&A4[lane + 32 * (4 * (bt + 1) + t)]);
                bb[cur ^ 1][t] = __ldcs(&B4[lane + 32 * (4 * (bt + 1) + t)]);
            }
        }
        #pragma unroll
        for (int t = 0; t < 4; ++t) {
            float4 v = sx4[lane + 32 * (4 * bt + t)];
            a0 = fmaf(ba[cur][t].x, v.x, a0);
            a1 = fmaf(ba[cur][t].y, v.y, a1);
            a2 = fmaf(ba[cur][t].z, v.z, a2);
            a3 = fmaf(ba[cur][t].w, v.w, a3);
            c0 = fmaf(bb[cur][t].x, v.x, c0);
            c1 = fmaf(bb[cur][t].y, v.y, c1);
            c2 = fmaf(bb[cur][t].z, v.z, c2);
            c3 = fmaf(bb[cur][t].w, v.w, c3);
        }
    }
    float accA = (a0 + a1) + (a2 + a3);
    float accB = (c0 + c1) + (c2 + c3);
    #pragma unroll
    for (int off = 16; off; off >>= 1) {
        accA += __shfl_xor_sync(0xFFFFFFFFu, accA, off);
        accB += __shfl_xor_sync(0xFFFFFFFFu, accB, off);
    }
    if (lane == 0) {
        y[row0] = act_apply<ACT>(accA + b[row0]);
        y[row1] = act_apply<ACT>(accB + b[row1]);
    }
}

// ---------------------------------------------------------------------------
// layer: stage x into smem; 2-row warps use the interleaved path
// ---------------------------------------------------------------------------
template<int ACT, int COLS, int ROWS>
__device__ __forceinline__ void layer(const float* __restrict__ W,
                                      const float* __restrict__ xg,
                                      const float* __restrict__ b,
                                      float* __restrict__ y,
                                      float* sx, int tid, int gw, int lane)
{
    const float4* __restrict__ xg4 = reinterpret_cast<const float4*>(xg);
    float4* sx4 = reinterpret_cast<float4*>(sx);
    for (int k = tid; k < COLS / 4; k += 256) sx4[k] = __ldg(&xg4[k]);
    __syncthreads();

    if (gw + NWARP < ROWS)
        dot_row2<ACT, COLS>(W, sx, b, y, gw, gw + NWARP, lane);
    else if (gw < ROWS)
        dot_row<ACT, COLS>(W, sx, b, y, gw, lane);
}

// ---------------------------------------------------------------------------
// warp-local pdist slice (no barriers), streaming stores
// ---------------------------------------------------------------------------
template<int DIMS>
__device__ __forceinline__ void pdist_warp(const float* __restrict__ s,
                                           float* __restrict__ outp,
                                           int gw, int lane)
{
    for (int idx = gw * 32 + lane; idx < NB * NB; idx += NWARP * 32) {
        const int i = idx >> 10;
        const int j = idx & (NB - 1);
        float d2 = 0.f;
        #pragma unroll
        for (int k = 0; k < DIMS; ++k) {
            float d = s[i * DIMS + k] - s[j * DIMS + k];
            d2 = fmaf(d, d, d2);
        }
        __stcs(&outp[idx], sqrtf(d2));
    }
}

// ---------------------------------------------------------------------------
// the whole network in one persistent kernel
// ---------------------------------------------------------------------------
__global__ void __launch_bounds__(256, 2)
fused_net(const float* __restrict__ x,
          const float* __restrict__ ew1, const float* __restrict__ eb1,
          const float* __restrict__ ew2, const float* __restrict__ eb2,
          const float* __restrict__ ew3, const float* __restrict__ eb3,
          const float* __restrict__ ew4, const float* __restrict__ eb4,
          const float* __restrict__ dw1, const float* __restrict__ db1,
          const float* __restrict__ dw2, const float* __restrict__ db2,
          const float* __restrict__ dw3, const float* __restrict__ db3,
          const float* __restrict__ dw4, const float* __restrict__ db4,
          float* __restrict__ out)
{
    __shared__ float sx[AA];    // 12 KB: layer input (x in L1, y in L5)

    const int tid  = threadIdx.x;
    const int bid  = blockIdx.x;
    const int lane = tid & 31;
    const int gw   = bid * 8 + (tid >> 5);

    float* out_main = out;                      // 3072
    float* out_ind  = out + AA;                 // 1024*1024
    float* out_lat  = out + AA + NB * NB;       // 1024*1024
    float* y        = out + AA + 2 * NB * NB;   // 2048 (lat_repr)

    // L1: x -> buf0 (tanh); bubble: pdist on in_data (sx == x)
    layer<1, AA, AA>(ew1, x, eb1, g_buf0, sx, tid, gw, lane);
    pdist_warp<3>(sx, out_ind, gw, lane);
    grid_bar(tid, NBLK * 1);

    // L2: buf0 -> buf1 (tanh)
    layer<1, AA, AA>(ew2, g_buf0, eb2, g_buf1, sx, tid, gw, lane);
    grid_bar(tid, NBLK * 2);

    // L3: buf1 -> buf0 (none)
    layer<0, AA, AA>(ew3, g_buf1, eb3, g_buf0, sx, tid, gw, lane);
    grid_bar(tid, NBLK * 3);

    // L4: buf0 -> y (tanhshrink, 2048 rows)
    layer<2, AA, DD>(ew4, g_buf0, eb4, y, sx, tid, gw, lane);
    grid_bar(tid, NBLK * 4);

    // L5: y -> buf0 (tanh, COLS=2048); bubble: pdist on lat_repr (sx == y)
    layer<1, DD, AA>(dw1, y, db1, g_buf0, sx, tid, gw, lane);
    pdist_warp<2>(sx, out_lat, gw, lane);
    grid_bar(tid, NBLK * 5);

    // L6: buf0 -> buf1 (tanh)
    layer<1, AA, AA>(dw2, g_buf0, db2, g_buf1, sx, tid, gw, lane);
    grid_bar(tid, NBLK * 6);

    // L7: buf1 -> buf0 (none)
    layer<0, AA, AA>(dw3, g_buf1, db3, g_buf0, sx, tid, gw, lane);
    grid_bar(tid, NBLK * 7);

    // L8: buf0 -> out_main (tanh)
    layer<1, AA, AA>(dw4, g_buf0, db4, out_main, sx, tid, gw, lane);

    // exit: last block resets barrier counters for next replay
    __syncthreads();
    if (tid == 0) {
        unsigned done = atomicAdd(&g_exit, 1u);
        if (done == NBLK - 1) {
            g_bar  = 0;
            g_exit = 0;
            __threadfence();
        }
    }
}

// ---------------------------------------------------------------------------
extern "C" void kernel_launch(void* const* d_in, const int* in_sizes, int n_in,
                              void* d_out, int out_size)
{
    (void)in_sizes; (void)n_in; (void)out_size;

    fused_net<<<NBLK, 256>>>(
        (const float*)d_in[0],
        (const float*)d_in[1],  (const float*)d_in[2],
        (const float*)d_in[3],  (const float*)d_in[4],
        (const float*)d_in[5],  (const float*)d_in[6],
        (const float*)d_in[7],  (const float*)d_in[8],
        (const float*)d_in[9],  (const float*)d_in[10],
        (const float*)d_in[11], (const float*)d_in[12],
        (const float*)d_in[13], (const float*)d_in[14],
        (const float*)d_in[15], (const float*)d_in[16],
        (float*)d_out);
}